// round 7
// baseline (speedup 1.0000x reference)
#include <cuda_runtime.h>
#include <math.h>
#include <float.h>

// ---------------- scratch (device globals; zero-initialized at load) -------
#define MAXC   128
#define MAXC2  256
#define MAXD   768
#define CPC    128            // cols per chunk
#define NCH    6              // 768 / 128
#define RS     24             // row splits
#define SEG_TPB 128

__device__ int      g_counts[MAXC];
__device__ float    g_part[(size_t)RS * 2 * NCH * 100 * CPC];  // [r][m][chunk][class][w]
__device__ float    g_znorm[MAXC2 * MAXD];                     // row-major
__device__ float    g_znormT[MAXD * MAXC2];                    // [k][j]
__device__ float    g_rowloss[MAXC2];
__device__ unsigned g_ctr2;

// ---------------- streaming segment-sum (no gather, no atomic floats) ------
// block (chunk, m, r): streams rows [r0, r1) of matrix m, cols chunk*128..+127,
// accumulating into smem acc[class][128]. Thread owns one column: no conflicts,
// no atomics, deterministic.

__global__ void __launch_bounds__(SEG_TPB)
k_segsum(const float* __restrict__ z1, const float* __restrict__ z2,
         const int* __restrict__ labels, int N, const int* __restrict__ task_id) {
    extern __shared__ float smem[];
    float* acc  = smem;                      // 100 * CPC floats
    int*   slab = (int*)(smem + 100 * CPC);  // per-block labels
    __shared__ int shist[MAXC];

    int end_i = (*task_id + 1) * 10;
    int chunk = blockIdx.x;
    int m     = blockIdx.y;
    int r     = blockIdx.z;
    const float* __restrict__ z = m ? z2 : z1;

    int per = (N + RS - 1) / RS;
    int r0 = r * per;
    int r1 = min(N, r0 + per);
    int nrows = r1 - r0;
    int tid = threadIdx.x;

    for (int t = tid; t < 100 * CPC; t += SEG_TPB) acc[t] = 0.f;
    for (int t = tid; t < MAXC; t += SEG_TPB) shist[t] = 0;
    for (int t = tid; t < nrows; t += SEG_TPB) slab[t] = labels[r0 + t];
    __syncthreads();

    const float* __restrict__ base = z + (size_t)r0 * MAXD + chunk * CPC + tid;

    int k = 0;
    for (; k + 16 <= nrows; k += 16) {
        float v[16];
#pragma unroll
        for (int u = 0; u < 16; u++)
            v[u] = __ldcs(base + (size_t)(k + u) * MAXD);
#pragma unroll
        for (int u = 0; u < 16; u++) {
            int lab = slab[k + u];
            if ((unsigned)lab < (unsigned)end_i)
                acc[lab * CPC + tid] += v[u];
        }
    }
    for (; k < nrows; k++) {
        float v = __ldcs(base + (size_t)k * MAXD);
        int lab = slab[k];
        if ((unsigned)lab < (unsigned)end_i)
            acc[lab * CPC + tid] += v;
    }
    __syncthreads();

    // write deterministic partials (coalesced)
    float* dst = g_part + ((((size_t)r * 2 + m) * NCH + chunk) * 100) * CPC;
    for (int t = tid; t < end_i * CPC; t += SEG_TPB) dst[t] = acc[t];

    // counts: designated blocks only (chunk 0, matrix 0); integer atomics
    if (chunk == 0 && m == 0) {
        for (int t = tid; t < nrows; t += SEG_TPB) {
            int lab = slab[t];
            if ((unsigned)lab < (unsigned)end_i) atomicAdd(&shist[lab], 1);
        }
        __syncthreads();
        if (tid < end_i && shist[tid]) atomicAdd(&g_counts[tid], shist[tid]);
    }
}

// ---------------- reduce partials + divide + normalize + transpose ---------

__global__ void __launch_bounds__(256)
k_norm(float* __restrict__ out, const int* __restrict__ task_id) {
    int end_i = (*task_id + 1) * 10;
    int C2    = 2 * end_i;
    int i = blockIdx.x;
    if (i >= C2) return;

    int m = (i >= end_i) ? 1 : 0;
    int c = m ? (i - end_i) : i;
    float inv = 1.0f / (float)max(g_counts[c], 1);
    int tid = threadIdx.x;

    const size_t rstep = (size_t)2 * NCH * 100 * CPC;   // per-r stride in g_part

    float v[3];
    float ssq = 0.f;
#pragma unroll
    for (int q = 0; q < 3; q++) {
        int col   = tid + 256 * q;
        int chunk = col >> 7;
        int w     = col & (CPC - 1);
        const float* __restrict__ p =
            g_part + (((size_t)m * NCH + chunk) * 100 + c) * CPC + w;
        float s = 0.f;
#pragma unroll
        for (int r = 0; r < RS; r++) s += p[(size_t)r * rstep];
        s *= inv;
        v[q] = s;
        ssq += s * s;
        out[1 + (size_t)i * MAXD + col] = s;
    }

    __shared__ float red[256];
    red[tid] = ssq;
    __syncthreads();
    for (int s = 128; s > 0; s >>= 1) {
        if (tid < s) red[tid] += red[tid + s];
        __syncthreads();
    }
    float scale = 1.0f / fmaxf(sqrtf(red[0]), 1e-12f);

#pragma unroll
    for (int q = 0; q < 3; q++) {
        int col = tid + 256 * q;
        float zn = v[q] * scale;
        g_znorm[(size_t)i * MAXD + col]   = zn;
        g_znormT[(size_t)col * MAXC2 + i] = zn;
    }
}

// ---------------- fused logits + softmax rowloss + final -------------------
// 50 blocks x 256 threads; block b handles rows 4b..4b+3.

#define LROWS 4
__global__ void __launch_bounds__(256)
k_loss(float* __restrict__ out, const int* __restrict__ task_id) {
    int end_i = (*task_id + 1) * 10;
    int C2    = 2 * end_i;
    int i0 = blockIdx.x * LROWS;
    int tid = threadIdx.x;

    __shared__ float srow[LROWS][MAXD];
    __shared__ float red[256];
    __shared__ float sh_m, sh_s;
    __shared__ int   shcnt[MAXC];
    __shared__ bool  lastblk;

    bool act = (i0 < C2);

    for (int t = tid; t < MAXC; t += 256) shcnt[t] = g_counts[t];
    if (act) {
        for (int t = tid; t < MAXD * LROWS; t += 256) {
            int rr = t / MAXD, cc = t % MAXD;
            srow[rr][cc] = g_znorm[(size_t)(i0 + rr) * MAXD + cc];
        }
    }
    __syncthreads();

    float lrow[LROWS] = {0.f, 0.f, 0.f, 0.f};
    if (act) {
        float p[LROWS][2];
#pragma unroll
        for (int r = 0; r < LROWS; r++) { p[r][0] = 0.f; p[r][1] = 0.f; }
        const float* __restrict__ zT = g_znormT;
#pragma unroll 1
        for (int k0 = 0; k0 < MAXD; k0 += 8) {
            float vv[8];
#pragma unroll
            for (int u = 0; u < 8; u++) vv[u] = zT[(size_t)(k0 + u) * MAXC2 + tid];
#pragma unroll
            for (int u = 0; u < 8; u++)
#pragma unroll
                for (int r = 0; r < LROWS; r++)
                    p[r][u & 1] = fmaf(srow[r][k0 + u], vv[u], p[r][u & 1]);
        }
#pragma unroll
        for (int r = 0; r < LROWS; r++) lrow[r] = (p[r][0] + p[r][1]) * 2.0f;
    }

    int  cls = (tid < end_i) ? tid : tid - end_i;
    bool vj  = (tid < C2) && (shcnt[cls] > 0);

    for (int rr = 0; rr < LROWS; rr++) {
        int   i  = i0 + rr;
        float lv = lrow[rr];
        if (act) {
            red[tid] = vj ? lv : -FLT_MAX;
            __syncthreads();
            for (int s = 128; s > 0; s >>= 1) {
                if (tid < s) red[tid] = fmaxf(red[tid], red[tid + s]);
                __syncthreads();
            }
            if (tid == 0) sh_m = red[0];
            __syncthreads();
            float m = sh_m;

            red[tid] = (vj && tid != i) ? expf(lv - m) : 0.f;
            __syncthreads();
            for (int s = 128; s > 0; s >>= 1) {
                if (tid < s) red[tid] += red[tid + s];
                __syncthreads();
            }
            if (tid == 0) sh_s = red[0];
            __syncthreads();
            float S = sh_s;

            int jpos = i + end_i;
            if (jpos >= C2) jpos -= C2;
            if (tid == jpos) {
                int  icls = (i < end_i) ? i : i - end_i;
                bool vi   = shcnt[icls] > 0;
                g_rowloss[i] = (vi && vj) ? ((lv - m) - logf(S)) : 0.f;
            }
            __syncthreads();
        }
    }

    __threadfence();
    if (tid == 0)
        lastblk = (atomicAdd(&g_ctr2, 1u) == gridDim.x - 1);
    __syncthreads();
    if (lastblk) {
        __threadfence();
        float l = (tid < C2) ? g_rowloss[tid] : 0.f;
        red[tid] = l;
        __syncthreads();
        for (int s = 128; s > 0; s >>= 1) {
            if (tid < s) red[tid] += red[tid + s];
            __syncthreads();
        }
        float lsum = red[0];
        __syncthreads();
        red[tid] = vj ? 1.f : 0.f;
        __syncthreads();
        for (int s = 128; s > 0; s >>= 1) {
            if (tid < s) red[tid] += red[tid + s];
            __syncthreads();
        }
        if (tid == 0) out[0] = -lsum / fmaxf(red[0], 1.0f);
        // reset persistent state for next call
        if (tid < MAXC) g_counts[tid] = 0;
        if (tid == 0)   g_ctr2 = 0;
    }
}

// ---------------- launch ----------------------------------------------------

extern "C" void kernel_launch(void* const* d_in, const int* in_sizes, int n_in,
                              void* d_out, int out_size) {
    const float* z1      = (const float*)d_in[0];
    const float* z2      = (const float*)d_in[1];
    const int*   labels  = (const int*)d_in[2];
    const int*   task_id = (const int*)d_in[3];
    float*       out     = (float*)d_out;

    int N = in_sizes[2];
    int per = (N + RS - 1) / RS;
    size_t smem_bytes = (size_t)100 * CPC * 4 + (size_t)(per + 4) * 4;

    static bool attr_set = false;
    if (!attr_set) {
        cudaFuncSetAttribute(k_segsum, cudaFuncAttributeMaxDynamicSharedMemorySize,
                             (int)(100 * CPC * 4 + 8192));
        attr_set = true;
    }

    dim3 gseg(NCH, 2, RS);
    k_segsum<<<gseg, SEG_TPB, smem_bytes>>>(z1, z2, labels, N, task_id);

    k_norm<<<200, 256>>>(out, task_id);
    k_loss<<<50, 256>>>(out, task_id);
}

// round 8
// speedup vs baseline: 1.0197x; 1.0197x over previous
#include <cuda_runtime.h>
#include <math.h>
#include <float.h>

// ---------------- scratch (device globals; zero-initialized at load) -------
#define MAXC   128
#define MAXC2  256
#define MAXD   768
#define CPC    128            // cols per chunk
#define NCH    6              // 768 / 128
#define RS     24             // row splits
#define SEG_TPB 128

__device__ int      g_counts[MAXC];
__device__ float    g_part[(size_t)RS * 2 * NCH * 100 * CPC];  // [r][m][chunk][class][w]
__device__ float    g_znorm[MAXC2 * MAXD];                     // row-major
__device__ float    g_znormT[MAXD * MAXC2];                    // [k][j]
__device__ float    g_rowloss[MAXC2];
__device__ unsigned g_ctr2;

// ---------------- streaming segment-sum (no gather, no atomic floats) ------
// block (chunk, m, r): streams rows [r0, r1) of matrix m, cols chunk*128..+127,
// accumulating into smem acc[class][128]. Thread owns one column: no conflicts,
// no atomics, deterministic.

__global__ void __launch_bounds__(SEG_TPB)
k_segsum(const float* __restrict__ z1, const float* __restrict__ z2,
         const int* __restrict__ labels, int N, const int* __restrict__ task_id) {
    extern __shared__ float smem[];
    float* acc  = smem;                      // 100 * CPC floats
    int*   slab = (int*)(smem + 100 * CPC);  // per-block labels
    __shared__ int shist[MAXC];

    int end_i = (*task_id + 1) * 10;
    int chunk = blockIdx.x;
    int m     = blockIdx.y;
    int r     = blockIdx.z;
    const float* __restrict__ z = m ? z2 : z1;

    int per = (N + RS - 1) / RS;
    int r0 = r * per;
    int r1 = min(N, r0 + per);
    int nrows = r1 - r0;
    int tid = threadIdx.x;

    for (int t = tid; t < 100 * CPC; t += SEG_TPB) acc[t] = 0.f;
    for (int t = tid; t < MAXC; t += SEG_TPB) shist[t] = 0;
    for (int t = tid; t < nrows; t += SEG_TPB) slab[t] = labels[r0 + t];
    __syncthreads();

    const float* __restrict__ base = z + (size_t)r0 * MAXD + chunk * CPC + tid;

    int k = 0;
    for (; k + 16 <= nrows; k += 16) {
        float v[16];
#pragma unroll
        for (int u = 0; u < 16; u++)
            v[u] = __ldcs(base + (size_t)(k + u) * MAXD);
#pragma unroll
        for (int u = 0; u < 16; u++) {
            int lab = slab[k + u];
            if ((unsigned)lab < (unsigned)end_i)
                acc[lab * CPC + tid] += v[u];
        }
    }
    for (; k < nrows; k++) {
        float v = __ldcs(base + (size_t)k * MAXD);
        int lab = slab[k];
        if ((unsigned)lab < (unsigned)end_i)
            acc[lab * CPC + tid] += v;
    }
    __syncthreads();

    // write deterministic partials (coalesced)
    float* dst = g_part + ((((size_t)r * 2 + m) * NCH + chunk) * 100) * CPC;
    for (int t = tid; t < end_i * CPC; t += SEG_TPB) dst[t] = acc[t];

    // counts: designated blocks only (chunk 0, matrix 0); integer atomics
    if (chunk == 0 && m == 0) {
        for (int t = tid; t < nrows; t += SEG_TPB) {
            int lab = slab[t];
            if ((unsigned)lab < (unsigned)end_i) atomicAdd(&shist[lab], 1);
        }
        __syncthreads();
        if (tid < end_i && shist[tid]) atomicAdd(&g_counts[tid], shist[tid]);
    }
}

// ---------------- reduce partials + divide + normalize + transpose ---------

__global__ void __launch_bounds__(256)
k_norm(float* __restrict__ out, const int* __restrict__ task_id) {
    int end_i = (*task_id + 1) * 10;
    int C2    = 2 * end_i;
    int i = blockIdx.x;
    if (i >= C2) return;

    int m = (i >= end_i) ? 1 : 0;
    int c = m ? (i - end_i) : i;
    float inv = 1.0f / (float)max(g_counts[c], 1);
    int tid = threadIdx.x;

    const size_t rstep = (size_t)2 * NCH * 100 * CPC;   // per-r stride in g_part

    float v[3];
    float ssq = 0.f;
#pragma unroll
    for (int q = 0; q < 3; q++) {
        int col   = tid + 256 * q;
        int chunk = col >> 7;
        int w     = col & (CPC - 1);
        const float* __restrict__ p =
            g_part + (((size_t)m * NCH + chunk) * 100 + c) * CPC + w;
        float s = 0.f;
#pragma unroll
        for (int r = 0; r < RS; r++) s += p[(size_t)r * rstep];
        s *= inv;
        v[q] = s;
        ssq += s * s;
        out[1 + (size_t)i * MAXD + col] = s;
    }

    __shared__ float red[256];
    red[tid] = ssq;
    __syncthreads();
    for (int s = 128; s > 0; s >>= 1) {
        if (tid < s) red[tid] += red[tid + s];
        __syncthreads();
    }
    float scale = 1.0f / fmaxf(sqrtf(red[0]), 1e-12f);

#pragma unroll
    for (int q = 0; q < 3; q++) {
        int col = tid + 256 * q;
        float zn = v[q] * scale;
        g_znorm[(size_t)i * MAXD + col]   = zn;
        g_znormT[(size_t)col * MAXC2 + i] = zn;
    }
}

// ---------------- fused logits + softmax rowloss + final -------------------
// 50 blocks x 256 threads; block b handles rows 4b..4b+3.

#define LROWS 4
__global__ void __launch_bounds__(256)
k_loss(float* __restrict__ out, const int* __restrict__ task_id) {
    int end_i = (*task_id + 1) * 10;
    int C2    = 2 * end_i;
    int i0 = blockIdx.x * LROWS;
    int tid = threadIdx.x;

    __shared__ float srow[LROWS][MAXD];
    __shared__ float red[256];
    __shared__ float sh_m, sh_s;
    __shared__ int   shcnt[MAXC];
    __shared__ bool  lastblk;

    bool act = (i0 < C2);

    for (int t = tid; t < MAXC; t += 256) shcnt[t] = g_counts[t];
    if (act) {
        for (int t = tid; t < MAXD * LROWS; t += 256) {
            int rr = t / MAXD, cc = t % MAXD;
            srow[rr][cc] = g_znorm[(size_t)(i0 + rr) * MAXD + cc];
        }
    }
    __syncthreads();

    float lrow[LROWS] = {0.f, 0.f, 0.f, 0.f};
    if (act) {
        float p[LROWS][2];
#pragma unroll
        for (int r = 0; r < LROWS; r++) { p[r][0] = 0.f; p[r][1] = 0.f; }
        const float* __restrict__ zT = g_znormT;
#pragma unroll 1
        for (int k0 = 0; k0 < MAXD; k0 += 8) {
            float vv[8];
#pragma unroll
            for (int u = 0; u < 8; u++) vv[u] = zT[(size_t)(k0 + u) * MAXC2 + tid];
#pragma unroll
            for (int u = 0; u < 8; u++)
#pragma unroll
                for (int r = 0; r < LROWS; r++)
                    p[r][u & 1] = fmaf(srow[r][k0 + u], vv[u], p[r][u & 1]);
        }
#pragma unroll
        for (int r = 0; r < LROWS; r++) lrow[r] = (p[r][0] + p[r][1]) * 2.0f;
    }

    int  cls = (tid < end_i) ? tid : tid - end_i;
    bool vj  = (tid < C2) && (shcnt[cls] > 0);

    for (int rr = 0; rr < LROWS; rr++) {
        int   i  = i0 + rr;
        float lv = lrow[rr];
        if (act) {
            red[tid] = vj ? lv : -FLT_MAX;
            __syncthreads();
            for (int s = 128; s > 0; s >>= 1) {
                if (tid < s) red[tid] = fmaxf(red[tid], red[tid + s]);
                __syncthreads();
            }
            if (tid == 0) sh_m = red[0];
            __syncthreads();
            float m = sh_m;

            red[tid] = (vj && tid != i) ? expf(lv - m) : 0.f;
            __syncthreads();
            for (int s = 128; s > 0; s >>= 1) {
                if (tid < s) red[tid] += red[tid + s];
                __syncthreads();
            }
            if (tid == 0) sh_s = red[0];
            __syncthreads();
            float S = sh_s;

            int jpos = i + end_i;
            if (jpos >= C2) jpos -= C2;
            if (tid == jpos) {
                int  icls = (i < end_i) ? i : i - end_i;
                bool vi   = shcnt[icls] > 0;
                g_rowloss[i] = (vi && vj) ? ((lv - m) - logf(S)) : 0.f;
            }
            __syncthreads();
        }
    }

    __threadfence();
    if (tid == 0)
        lastblk = (atomicAdd(&g_ctr2, 1u) == gridDim.x - 1);
    __syncthreads();
    if (lastblk) {
        __threadfence();
        float l = (tid < C2) ? g_rowloss[tid] : 0.f;
        red[tid] = l;
        __syncthreads();
        for (int s = 128; s > 0; s >>= 1) {
            if (tid < s) red[tid] += red[tid + s];
            __syncthreads();
        }
        float lsum = red[0];
        __syncthreads();
        red[tid] = vj ? 1.f : 0.f;
        __syncthreads();
        for (int s = 128; s > 0; s >>= 1) {
            if (tid < s) red[tid] += red[tid + s];
            __syncthreads();
        }
        if (tid == 0) out[0] = -lsum / fmaxf(red[0], 1.0f);
        // reset persistent state for next call
        if (tid < MAXC) g_counts[tid] = 0;
        if (tid == 0)   g_ctr2 = 0;
    }
}

// ---------------- launch ----------------------------------------------------

extern "C" void kernel_launch(void* const* d_in, const int* in_sizes, int n_in,
                              void* d_out, int out_size) {
    const float* z1      = (const float*)d_in[0];
    const float* z2      = (const float*)d_in[1];
    const int*   labels  = (const int*)d_in[2];
    const int*   task_id = (const int*)d_in[3];
    float*       out     = (float*)d_out;

    int N = in_sizes[2];
    int per = (N + RS - 1) / RS;
    size_t smem_bytes = (size_t)100 * CPC * 4 + (size_t)(per + 4) * 4;

    static bool attr_set = false;
    if (!attr_set) {
        cudaFuncSetAttribute(k_segsum, cudaFuncAttributeMaxDynamicSharedMemorySize,
                             (int)(100 * CPC * 4 + 8192));
        attr_set = true;
    }

    dim3 gseg(NCH, 2, RS);
    k_segsum<<<gseg, SEG_TPB, smem_bytes>>>(z1, z2, labels, N, task_id);

    k_norm<<<200, 256>>>(out, task_id);
    k_loss<<<50, 256>>>(out, task_id);
}